// round 6
// baseline (speedup 1.0000x reference)
#include <cuda_runtime.h>
#include <cstdint>
#include <climits>

#define T_STEPS 200
#define B_SZ    256
#define IN_SZ   784
#define N_SZ    400

#define ALPHA      0.9f
#define BETA       0.8f
#define THRESH     1.0f
#define BETA_PLUS  0.9f
#define BETA_MINUS 0.9f
#define A_PLUS     1e-3f
#define A_MINUS    1e-3f
#define LI_STR     0.1f

// ---------------- persistent device state ----------------
__device__ float g_Wt[IN_SZ * N_SZ];       // W transposed: Wt[k*N + n] = W[n, k]
__device__ float g_syn[B_SZ * N_SZ];
__device__ float g_mem[B_SZ * N_SZ];
__device__ float g_post[B_SZ * N_SZ];
__device__ float g_trT[IN_SZ * B_SZ];      // TRANSPOSED pre-trace: trT[k*B + b] = tr_t[b,k]
__device__ int   g_win[B_SZ];
__device__ int   g_flag[T_STEPS];
__device__ int   g_imgcnt[IN_SZ];
__device__ int   g_imglist[IN_SZ * B_SZ];              // per input k: batch rows with img=1
__device__ __align__(16) unsigned g_spkmask[N_SZ * 8]; // per neuron n: 256-bit spike mask over b

// ---------------- init ----------------
__global__ void k_init(const float* __restrict__ W) {
    int idx = blockIdx.x * blockDim.x + threadIdx.x;
    int stride = gridDim.x * blockDim.x;
    for (int j = idx; j < IN_SZ * N_SZ; j += stride) {
        int k = j / N_SZ, n = j % N_SZ;
        g_Wt[j] = W[n * IN_SZ + k];
    }
    for (int j = idx; j < B_SZ * N_SZ; j += stride) {
        g_syn[j] = 0.f; g_mem[j] = 0.f; g_post[j] = 0.f;
    }
    for (int j = idx; j < IN_SZ * B_SZ; j += stride) g_trT[j] = 0.f;
    for (int j = idx; j < T_STEPS; j += stride) g_flag[j] = 0;
}

// ---------------- K1: neuron update (one block per batch row) ----------------
__global__ void __launch_bounds__(512) k_neuron(const float* __restrict__ img, int t,
                                                float* __restrict__ memrec,
                                                float* __restrict__ spkrec) {
    int b = blockIdx.x;
    int tid = threadIdx.x;

    __shared__ float simg[IN_SZ];
    __shared__ int   s_act[IN_SZ];
    __shared__ int   s_cnt;
    __shared__ int   s_win;
    __shared__ int   s_any;

    const float* imgt = img + ((size_t)t * B_SZ + b) * IN_SZ;
    for (int k = tid; k < IN_SZ; k += 512) simg[k] = imgt[k];
    if (tid == 0) { s_win = INT_MAX; s_any = 0; }
    __syncthreads();

    // warp 0: order-preserving compaction of active input indices
    if (tid < 32) {
        int base = 0;
        for (int c = 0; c < (IN_SZ + 31) / 32; c++) {
            int k = c * 32 + tid;
            bool act = (k < IN_SZ) && (simg[k] != 0.0f);
            unsigned m = __ballot_sync(0xffffffffu, act);
            if (act) s_act[base + __popc(m & ((1u << tid) - 1u))] = k;
            base += __popc(m);
        }
        if (tid == 0) s_cnt = base;
    }
    __syncthreads();

    int cnt = s_cnt;
    if (tid < N_SZ) {
        int n = tid;
        float cur = 0.f;
        for (int i = 0; i < cnt; i++) cur += g_Wt[s_act[i] * N_SZ + n];

        float m = g_mem[b * N_SZ + n];
        float s = g_syn[b * N_SZ + n];
        float reset = (m > THRESH) ? 1.0f : 0.0f;
        s = ALPHA * s + cur;
        m = BETA * m + s - reset * THRESH;
        float spk = (m > THRESH) ? 1.0f : 0.0f;

        size_t rec = ((size_t)t * B_SZ + b) * N_SZ + n;
        memrec[rec] = m;
        spkrec[rec] = spk;
        g_syn[b * N_SZ + n] = s;
        g_mem[b * N_SZ + n] = m;

        if (spk != 0.f) { atomicMin(&s_win, n); s_any = 1; }
    }
    __syncthreads();
    if (tid == 0) {
        g_win[b] = (s_win == INT_MAX) ? 0 : s_win;
        if (s_any) atomicOr(&g_flag[t], 1);
    }
}

// ---------------- K2: prep ----------------
// Blocks [0,98):    img-active lists per k (8 warps x 98 = 784)
// Blocks [98,148):  spike bitmasks per n (8 warps x 50 = 400)
// Blocks [148,548): element-wise LI + post-trace update over [B,N]
// Blocks [548,748): transposed trace update trT = bp*trT + img[t-1]^T (32x32 tiles)
#define PREP_IMG  98
#define PREP_MSK  148
#define PREP_LI   548
#define PREP_TOT  748
__global__ void __launch_bounds__(256) k_prep(const float* __restrict__ img,
                                              const float* __restrict__ spkrec, int t) {
    int bid = blockIdx.x;
    int tid = threadIdx.x;

    if (bid < PREP_IMG) {
        int w = tid >> 5, lane = tid & 31;
        int k = bid * 8 + w;
        const float* imgt = img + (size_t)t * B_SZ * IN_SZ;
        int base = 0;
        for (int c = 0; c < B_SZ / 32; c++) {
            int b = c * 32 + lane;
            bool a = imgt[(size_t)b * IN_SZ + k] != 0.0f;
            unsigned m = __ballot_sync(0xffffffffu, a);
            if (a) g_imglist[k * B_SZ + base + __popc(m & ((1u << lane) - 1u))] = b;
            base += __popc(m);
        }
        if (lane == 0) g_imgcnt[k] = base;
    } else if (bid < PREP_MSK) {
        int w = tid >> 5, lane = tid & 31;
        int n = (bid - PREP_IMG) * 8 + w;
        const float* spkt = spkrec + (size_t)t * B_SZ * N_SZ;
        for (int c = 0; c < B_SZ / 32; c++) {
            int b = c * 32 + lane;
            bool a = spkt[b * N_SZ + n] != 0.0f;
            unsigned m = __ballot_sync(0xffffffffu, a);
            if (lane == 0) g_spkmask[n * 8 + c] = m;
        }
    } else if (bid < PREP_LI) {
        int idx = (bid - PREP_MSK) * 256 + tid;
        if (idx < B_SZ * N_SZ) {
            int b = idx / N_SZ, n = idx % N_SZ;
            float spk = spkrec[(size_t)t * B_SZ * N_SZ + idx];
            if (g_flag[t]) {
                if (n != g_win[b]) g_syn[idx] -= LI_STR;
            }
            g_post[idx] = BETA_MINUS * g_post[idx] + spk;
        }
    } else {
        if (t == 0) return;   // trT stays zero for step 0
        int d = bid - PREP_LI;             // 0..199
        int kt = d % 25, bt = d / 25;      // 25 k-tiles x 8 b-tiles
        int k0 = kt * 32, b0 = bt * 32;
        __shared__ float s[32][33];
        int tx = tid & 31, ty = tid >> 5;  // ty 0..7
        const float* imgp = img + (size_t)(t - 1) * B_SZ * IN_SZ;
#pragma unroll
        for (int r = 0; r < 4; r++) {
            int bl = ty + r * 8;           // local b
            int k = k0 + tx;
            s[bl][tx] = (k < IN_SZ) ? imgp[(size_t)(b0 + bl) * IN_SZ + k] : 0.f;
        }
        __syncthreads();
#pragma unroll
        for (int r = 0; r < 4; r++) {
            int kl = ty + r * 8;           // local k
            int k = k0 + kl;
            if (k < IN_SZ) {
                int j = k * B_SZ + b0 + tx;
                g_trT[j] = BETA_PLUS * g_trT[j] + s[tx][kl];
            }
        }
    }
}

// ---------------- K3: fused STDP update, one block per input k ----------------
// Wt[k,n] = clip(Wt[k,n] + A_PLUS * sum_{b: spk[b,n]=1} trT[k,b]
//                        - A_MINUS * sum_{b: img[b,k]=1} post[b,n], 0, 1)
__global__ void __launch_bounds__(416) k_stdp() {
    int k = blockIdx.x;
    int tid = threadIdx.x;

    __shared__ float s_tr[B_SZ];
    __shared__ float s_ps[8];      // per-32-chunk partial sums of s_tr
    __shared__ int   s_list[B_SZ];
    __shared__ int   s_icnt;

    if (tid < B_SZ) s_tr[tid] = g_trT[k * B_SZ + tid];
    if (tid == 0) s_icnt = g_imgcnt[k];
    __syncthreads();

    // deterministic per-chunk reduction (fixed shfl tree)
    if (tid < B_SZ) {
        float v = s_tr[tid];
#pragma unroll
        for (int off = 16; off > 0; off >>= 1)
            v += __shfl_xor_sync(0xffffffffu, v, off);
        if ((tid & 31) == 0) s_ps[tid >> 5] = v;
    }
    int icnt = s_icnt;
    for (int i = tid; i < icnt; i += 416) s_list[i] = g_imglist[k * B_SZ + i];
    __syncthreads();

    int n = tid;
    if (n < N_SZ) {
        // LTP via spike bitmask over smem trace row
        const uint4* mp = reinterpret_cast<const uint4*>(&g_spkmask[n * 8]);
        uint4 m0 = mp[0], m1 = mp[1];
        unsigned mw[8] = {m0.x, m0.y, m0.z, m0.w, m1.x, m1.y, m1.z, m1.w};
        float ltp = 0.f;
#pragma unroll
        for (int w = 0; w < 8; w++) {
            unsigned m = mw[w];
            if (m == 0xffffffffu) {
                ltp += s_ps[w];
            } else if (m) {
                const float* base = s_tr + w * 32;
                do {
                    int b = __ffs(m) - 1;
                    m &= m - 1;
                    ltp += base[b];
                } while (m);
            }
        }

        // LTD via img-active list, coalesced over n
        float ltd = 0.f;
        for (int i = 0; i < icnt; i++) ltd += g_post[s_list[i] * N_SZ + n];

        float w = g_Wt[k * N_SZ + n];
        w = w + A_PLUS * ltp - A_MINUS * ltd;
        w = fminf(fmaxf(w, 0.f), 1.f);
        g_Wt[k * N_SZ + n] = w;
    }
}

// ---------------- final: transpose Wt back into output layout [N, IN] ----------------
__global__ void k_write_w(float* __restrict__ outW) {
    int idx = blockIdx.x * blockDim.x + threadIdx.x;
    if (idx >= N_SZ * IN_SZ) return;
    int n = idx / IN_SZ, k = idx % IN_SZ;
    outW[idx] = g_Wt[k * N_SZ + n];
}

// ---------------- launch ----------------
extern "C" void kernel_launch(void* const* d_in, const int* in_sizes, int n_in,
                              void* d_out, int out_size) {
    const float* img = (const float*)d_in[0];
    const float* W   = (const float*)d_in[1];
    if (n_in >= 2 && in_sizes[0] == N_SZ * IN_SZ) {
        const float* tmp = img; img = W; W = tmp;
    }

    float* out = (float*)d_out;
    float* memrec = out;
    float* spkrec = out + (size_t)T_STEPS * B_SZ * N_SZ;
    float* outW   = out + 2 * (size_t)T_STEPS * B_SZ * N_SZ;

    k_init<<<256, 256>>>(W);

    for (int t = 0; t < T_STEPS; t++) {
        k_neuron<<<B_SZ, 512>>>(img, t, memrec, spkrec);
        k_prep<<<PREP_TOT, 256>>>(img, spkrec, t);
        k_stdp<<<IN_SZ, 416>>>();
    }
    k_write_w<<<(N_SZ * IN_SZ + 255) / 256, 256>>>(outW);
}

// round 7
// speedup vs baseline: 1.0063x; 1.0063x over previous
#include <cuda_runtime.h>
#include <cstdint>
#include <climits>

#define T_STEPS 200
#define B_SZ    256
#define IN_SZ   784
#define N_SZ    400

#define ALPHA      0.9f
#define BETA       0.8f
#define THRESH     1.0f
#define BETA_PLUS  0.9f
#define BETA_MINUS 0.9f
#define A_PLUS     1e-3f
#define A_MINUS    1e-3f
#define LI_STR     0.1f

// ---------------- persistent device state ----------------
__device__ float g_Wt[IN_SZ * N_SZ];       // W transposed: Wt[k*N + n] = W[n, k]
__device__ float g_syn[B_SZ * N_SZ];
__device__ float g_mem[B_SZ * N_SZ];
__device__ float g_post[B_SZ * N_SZ];
__device__ float g_trT[IN_SZ * B_SZ];      // TRANSPOSED pre-trace: trT[k*B + b] = tr_t[b,k]
__device__ int   g_win[B_SZ];
__device__ int   g_flag[T_STEPS];
__device__ int   g_imgcnt[IN_SZ];
__device__ int   g_imglist[IN_SZ * B_SZ];              // per input k: batch rows with img=1
__device__ __align__(16) unsigned g_spkmask[N_SZ * 8]; // per neuron n: 256-bit spike mask over b

// ---------------- init ----------------
__global__ void k_init(const float* __restrict__ W) {
    int idx = blockIdx.x * blockDim.x + threadIdx.x;
    int stride = gridDim.x * blockDim.x;
    for (int j = idx; j < IN_SZ * N_SZ; j += stride) {
        int k = j / N_SZ, n = j % N_SZ;
        g_Wt[j] = W[n * IN_SZ + k];
    }
    for (int j = idx; j < B_SZ * N_SZ; j += stride) {
        g_syn[j] = 0.f; g_mem[j] = 0.f; g_post[j] = 0.f;
    }
    for (int j = idx; j < IN_SZ * B_SZ; j += stride) g_trT[j] = 0.f;
    for (int j = idx; j < T_STEPS; j += stride) g_flag[j] = 0;
}

// ---------------- K1: neuron update (one block per batch row) ----------------
__global__ void __launch_bounds__(512) k_neuron(const float* __restrict__ img, int t,
                                                float* __restrict__ memrec,
                                                float* __restrict__ spkrec) {
    int b = blockIdx.x;
    int tid = threadIdx.x;

    __shared__ float simg[IN_SZ];
    __shared__ int   s_act[IN_SZ];
    __shared__ int   s_cnt;
    __shared__ int   s_win;
    __shared__ int   s_any;

    const float* imgt = img + ((size_t)t * B_SZ + b) * IN_SZ;
    for (int k = tid; k < IN_SZ; k += 512) simg[k] = imgt[k];
    if (tid == 0) { s_win = INT_MAX; s_any = 0; }
    __syncthreads();

    // warp 0: order-preserving compaction of active input indices
    if (tid < 32) {
        int base = 0;
        for (int c = 0; c < (IN_SZ + 31) / 32; c++) {
            int k = c * 32 + tid;
            bool act = (k < IN_SZ) && (simg[k] != 0.0f);
            unsigned m = __ballot_sync(0xffffffffu, act);
            if (act) s_act[base + __popc(m & ((1u << tid) - 1u))] = k;
            base += __popc(m);
        }
        if (tid == 0) s_cnt = base;
    }
    __syncthreads();

    int cnt = s_cnt;
    if (tid < N_SZ) {
        int n = tid;
        float cur = 0.f;
        for (int i = 0; i < cnt; i++) cur += g_Wt[s_act[i] * N_SZ + n];

        float m = g_mem[b * N_SZ + n];
        float s = g_syn[b * N_SZ + n];
        float reset = (m > THRESH) ? 1.0f : 0.0f;
        s = ALPHA * s + cur;
        m = BETA * m + s - reset * THRESH;
        float spk = (m > THRESH) ? 1.0f : 0.0f;

        size_t rec = ((size_t)t * B_SZ + b) * N_SZ + n;
        memrec[rec] = m;
        spkrec[rec] = spk;
        g_syn[b * N_SZ + n] = s;
        g_mem[b * N_SZ + n] = m;

        if (spk != 0.f) { atomicMin(&s_win, n); s_any = 1; }
    }
    __syncthreads();
    if (tid == 0) {
        g_win[b] = (s_win == INT_MAX) ? 0 : s_win;
        if (s_any) atomicOr(&g_flag[t], 1);
    }
}

// ---------------- K2: prep ----------------
// Blocks [0,98):    img-active lists per k (8 warps x 98 = 784)
// Blocks [98,148):  spike bitmasks per n (8 warps x 50 = 400)
// Blocks [148,548): element-wise LI + post-trace update over [B,N]
// Blocks [548,748): transposed trace update trT = bp*trT + img[t-1]^T (32x32 tiles)
#define PREP_IMG  98
#define PREP_MSK  148
#define PREP_LI   548
#define PREP_TOT  748
__global__ void __launch_bounds__(256) k_prep(const float* __restrict__ img,
                                              const float* __restrict__ spkrec, int t) {
    int bid = blockIdx.x;
    int tid = threadIdx.x;

    if (bid < PREP_IMG) {
        int w = tid >> 5, lane = tid & 31;
        int k = bid * 8 + w;
        const float* imgt = img + (size_t)t * B_SZ * IN_SZ;
        int base = 0;
        for (int c = 0; c < B_SZ / 32; c++) {
            int b = c * 32 + lane;
            bool a = imgt[(size_t)b * IN_SZ + k] != 0.0f;
            unsigned m = __ballot_sync(0xffffffffu, a);
            if (a) g_imglist[k * B_SZ + base + __popc(m & ((1u << lane) - 1u))] = b;
            base += __popc(m);
        }
        if (lane == 0) g_imgcnt[k] = base;
    } else if (bid < PREP_MSK) {
        int w = tid >> 5, lane = tid & 31;
        int n = (bid - PREP_IMG) * 8 + w;
        const float* spkt = spkrec + (size_t)t * B_SZ * N_SZ;
        for (int c = 0; c < B_SZ / 32; c++) {
            int b = c * 32 + lane;
            bool a = spkt[b * N_SZ + n] != 0.0f;
            unsigned m = __ballot_sync(0xffffffffu, a);
            if (lane == 0) g_spkmask[n * 8 + c] = m;
        }
    } else if (bid < PREP_LI) {
        int idx = (bid - PREP_MSK) * 256 + tid;
        if (idx < B_SZ * N_SZ) {
            int b = idx / N_SZ, n = idx % N_SZ;
            float spk = spkrec[(size_t)t * B_SZ * N_SZ + idx];
            if (g_flag[t]) {
                if (n != g_win[b]) g_syn[idx] -= LI_STR;
            }
            g_post[idx] = BETA_MINUS * g_post[idx] + spk;
        }
    } else {
        if (t == 0) return;   // trT stays zero for step 0
        int d = bid - PREP_LI;             // 0..199
        int kt = d % 25, bt = d / 25;      // 25 k-tiles x 8 b-tiles
        int k0 = kt * 32, b0 = bt * 32;
        __shared__ float s[32][33];
        int tx = tid & 31, ty = tid >> 5;  // ty 0..7
        const float* imgp = img + (size_t)(t - 1) * B_SZ * IN_SZ;
#pragma unroll
        for (int r = 0; r < 4; r++) {
            int bl = ty + r * 8;           // local b
            int k = k0 + tx;
            s[bl][tx] = (k < IN_SZ) ? imgp[(size_t)(b0 + bl) * IN_SZ + k] : 0.f;
        }
        __syncthreads();
#pragma unroll
        for (int r = 0; r < 4; r++) {
            int kl = ty + r * 8;           // local k
            int k = k0 + kl;
            if (k < IN_SZ) {
                int j = k * B_SZ + b0 + tx;
                g_trT[j] = BETA_PLUS * g_trT[j] + s[tx][kl];
            }
        }
    }
}

// ---------------- K3: fused STDP update, one block per input k ----------------
// Wt[k,n] = clip(Wt[k,n] + A_PLUS * sum_{b: spk[b,n]=1} trT[k,b]
//                        - A_MINUS * sum_{b: img[b,k]=1} post[b,n], 0, 1)
__global__ void __launch_bounds__(416) k_stdp() {
    int k = blockIdx.x;
    int tid = threadIdx.x;

    __shared__ float s_tr[B_SZ];
    __shared__ float s_ps[8];      // per-32-chunk partial sums of s_tr
    __shared__ int   s_list[B_SZ];
    __shared__ int   s_icnt;

    if (tid < B_SZ) s_tr[tid] = g_trT[k * B_SZ + tid];
    if (tid == 0) s_icnt = g_imgcnt[k];
    __syncthreads();

    // deterministic per-chunk reduction (fixed shfl tree)
    if (tid < B_SZ) {
        float v = s_tr[tid];
#pragma unroll
        for (int off = 16; off > 0; off >>= 1)
            v += __shfl_xor_sync(0xffffffffu, v, off);
        if ((tid & 31) == 0) s_ps[tid >> 5] = v;
    }
    int icnt = s_icnt;
    for (int i = tid; i < icnt; i += 416) s_list[i] = g_imglist[k * B_SZ + i];
    __syncthreads();

    int n = tid;
    if (n < N_SZ) {
        // LTP via spike bitmask over smem trace row
        const uint4* mp = reinterpret_cast<const uint4*>(&g_spkmask[n * 8]);
        uint4 m0 = mp[0], m1 = mp[1];
        unsigned mw[8] = {m0.x, m0.y, m0.z, m0.w, m1.x, m1.y, m1.z, m1.w};
        float ltp = 0.f;
#pragma unroll
        for (int w = 0; w < 8; w++) {
            unsigned m = mw[w];
            if (m == 0xffffffffu) {
                ltp += s_ps[w];
            } else if (m) {
                const float* base = s_tr + w * 32;
                do {
                    int b = __ffs(m) - 1;
                    m &= m - 1;
                    ltp += base[b];
                } while (m);
            }
        }

        // LTD via img-active list, coalesced over n
        float ltd = 0.f;
        for (int i = 0; i < icnt; i++) ltd += g_post[s_list[i] * N_SZ + n];

        float w = g_Wt[k * N_SZ + n];
        w = w + A_PLUS * ltp - A_MINUS * ltd;
        w = fminf(fmaxf(w, 0.f), 1.f);
        g_Wt[k * N_SZ + n] = w;
    }
}

// ---------------- final: transpose Wt back into output layout [N, IN] ----------------
__global__ void k_write_w(float* __restrict__ outW) {
    int idx = blockIdx.x * blockDim.x + threadIdx.x;
    if (idx >= N_SZ * IN_SZ) return;
    int n = idx / IN_SZ, k = idx % IN_SZ;
    outW[idx] = g_Wt[k * N_SZ + n];
}

// ---------------- launch ----------------
extern "C" void kernel_launch(void* const* d_in, const int* in_sizes, int n_in,
                              void* d_out, int out_size) {
    const float* img = (const float*)d_in[0];
    const float* W   = (const float*)d_in[1];
    if (n_in >= 2 && in_sizes[0] == N_SZ * IN_SZ) {
        const float* tmp = img; img = W; W = tmp;
    }

    float* out = (float*)d_out;
    float* memrec = out;
    float* spkrec = out + (size_t)T_STEPS * B_SZ * N_SZ;
    float* outW   = out + 2 * (size_t)T_STEPS * B_SZ * N_SZ;

    k_init<<<256, 256>>>(W);

    for (int t = 0; t < T_STEPS; t++) {
        k_neuron<<<B_SZ, 512>>>(img, t, memrec, spkrec);
        k_prep<<<PREP_TOT, 256>>>(img, spkrec, t);
        k_stdp<<<IN_SZ, 416>>>();
    }
    k_write_w<<<(N_SZ * IN_SZ + 255) / 256, 256>>>(outW);
}